// round 1
// baseline (speedup 1.0000x reference)
#include <cuda_runtime.h>
#include <cstdint>

// ---------------------------------------------------------------------------
// SpaceTimeLookTable fused kernel, round 1.
//   Per CTA: 64 points, full K=12240 (padded to 12288) streamed in 192 chunks
//   of 64. Features are gathered/relu'd/tf32-rounded into SMEM, the (rms_scale
//   * w_down) chunk likewise, then warp-level mma.sync m16n8k8 tf32 accumulates
//   h_pre[64pts x 64] in registers. sumsq per point accumulated on the fly.
//   Epilogue: h = relu(h_pre / (rms+eps)), tiny final layer + sigmoid.
// ---------------------------------------------------------------------------

#define MPTS   64      // points per CTA
#define KC     64      // K chunk
#define KPAD   12288
#define NCHUNK (KPAD / KC)
#define SA     68      // smem row stride (floats), padded vs 64

__constant__ int c_OFF7[7][3] = {
    {0,0,0},{1,0,0},{-1,0,0},{0,1,0},{0,-1,0},{0,0,1},{0,0,-1}};
__constant__ int c_FACE[6][3] = {
    {1,0,0},{-1,0,0},{0,1,0},{0,-1,0},{0,0,1},{0,0,-1}};
__constant__ int c_CORNER[8][3] = {
    {1,1,1},{-1,-1,-1},{1,-1,-1},{-1,1,1},{1,1,-1},{-1,-1,1},{1,-1,1},{-1,1,-1}};
__constant__ int c_ETEMP[11] = {-64,-8,-4,-2,-1,0,1,2,4,8,64};

__device__ __forceinline__ uint32_t f2tf32(float x) {
    uint32_t u;
    asm("cvt.rna.tf32.f32 %0, %1;" : "=r"(u) : "f"(x));
    return u;
}

__device__ __forceinline__ void mma8(float* c,
                                     uint32_t a0, uint32_t a1, uint32_t a2, uint32_t a3,
                                     uint32_t b0, uint32_t b1) {
    asm("mma.sync.aligned.m16n8k8.row.col.f32.tf32.tf32.f32 "
        "{%0,%1,%2,%3}, {%4,%5,%6,%7}, {%8,%9}, {%0,%1,%2,%3};"
        : "+f"(c[0]), "+f"(c[1]), "+f"(c[2]), "+f"(c[3])
        : "r"(a0), "r"(a1), "r"(a2), "r"(a3), "r"(b0), "r"(b1));
}

// Gather 4 consecutive features [k, k+4) for point described by pi[] (smem).
// Segment boundaries (all multiples of 4, so a float4 never straddles one):
//   [0,112)      table0 128^3 x16, 7 offsets
//   [112,560)    table1  64^3 x64
//   [560,2352)   table2  32^3 x256
//   [2352,9520)  table3  16^3 x1024
//   [9520,11312) st1 (16,16,16,64)x64, 28 offsets
//   [11312,11536)st2 (64,64,64,64)x8, 28 offsets
//   [11536,12240)tf3 (4,4,4,65536)x8, 88 offsets
//   [12240,12288) zero pad
__device__ __forceinline__ float4 gather4(
    int k, const int* __restrict__ pi,
    const float* __restrict__ T0, const float* __restrict__ T1,
    const float* __restrict__ T2, const float* __restrict__ T3,
    const float* __restrict__ S1t, const float* __restrict__ S2t,
    const float* __restrict__ TF)
{
    if (k < 9520) {
        const float* tab; int r, flog, dlog, ix, iy, iz;
        if (k < 112)       { tab = T0; r = k;        flog = 4;  dlog = 7; ix = pi[0]; iy = pi[1];  iz = pi[2];  }
        else if (k < 560)  { tab = T1; r = k - 112;  flog = 6;  dlog = 6; ix = pi[3]; iy = pi[4];  iz = pi[5];  }
        else if (k < 2352) { tab = T2; r = k - 560;  flog = 8;  dlog = 5; ix = pi[6]; iy = pi[7];  iz = pi[8];  }
        else               { tab = T3; r = k - 2352; flog = 10; dlog = 4; ix = pi[9]; iy = pi[10]; iz = pi[11]; }
        int o = r >> flog;
        int f = r & ((1 << flog) - 1);
        int d = 1 << dlog, m = d - 1;
        int cx = (ix + c_OFF7[o][0] + d) & m;
        int cy = (iy + c_OFF7[o][1] + d) & m;
        int cz = (iz + c_OFF7[o][2] + d) & m;
        int addr = (((((cx << dlog) | cy) << dlog) | cz) << flog) + f;
        return *reinterpret_cast<const float4*>(tab + addr);
    }
    if (k < 12240) {
        int tb = pi[12], tv = pi[13];
        if (k < 11536) {
            bool is1 = (k < 11312);
            int r, o, f;
            if (is1) { r = k - 9520;  o = r >> 6; f = r & 63; }
            else     { r = k - 11312; o = r >> 3; f = r & 7;  }
            int sx, sy, sz;
            if (o < 12) { int i = o >> 1;        sx = c_FACE[i][0];   sy = c_FACE[i][1];   sz = c_FACE[i][2];   }
            else        { int i = (o - 12) >> 1; sx = c_CORNER[i][0]; sy = c_CORNER[i][1]; sz = c_CORNER[i][2]; }
            int st = (o & 1) ? -1 : 1;
            if (is1) {   // dims (16,16,16,64), F=64
                int a  = (tb + sx + 16) & 15;
                int b  = (tb + sy + 16) & 15;
                int c  = (tb + sz + 16) & 15;
                int dd = (tv + st + 64) & 63;
                int addr = (((((((a << 4) | b) << 4) | c) << 6) | dd) << 6) + f;
                return *reinterpret_cast<const float4*>(S1t + addr);
            } else {     // dims (64,64,64,64), F=8
                int a  = (tb + sx + 64) & 63;
                int b  = (tb + sy + 64) & 63;
                int c  = (tb + sz + 64) & 63;
                int dd = (tv + st + 64) & 63;
                int addr = (((((((a << 6) | b) << 6) | c) << 6) | dd) << 3) + f;
                return *reinterpret_cast<const float4*>(S2t + addr);
            }
        } else {         // tf3: dims (4,4,4,65536), F=8
            int r = k - 11536;
            int o = r >> 3, f = r & 7;
            int ci = o / 11, ti = o - ci * 11;
            int sx = c_CORNER[ci][0], sy = c_CORNER[ci][1], sz = c_CORNER[ci][2];
            int st = c_ETEMP[ti];
            int a  = (tb + sx + 4) & 3;
            int b  = (tb + sy + 4) & 3;
            int c  = (tb + sz + 4) & 3;
            int dd = (tv + st + 65536) & 65535;
            int addr = (((((((a << 2) | b) << 2) | c) << 16) | dd) << 3) + f;
            return *reinterpret_cast<const float4*>(TF + addr);
        }
    }
    return make_float4(0.f, 0.f, 0.f, 0.f);
}

__global__ void __launch_bounds__(256, 1)
stlt_fused_kernel(
    const float* __restrict__ d_pos, const float* __restrict__ d_dir,
    const float* __restrict__ d_t,
    const float* __restrict__ T0, const float* __restrict__ T1,
    const float* __restrict__ T2, const float* __restrict__ T3,
    const float* __restrict__ S1t, const float* __restrict__ S2t,
    const float* __restrict__ TF,
    const float* __restrict__ rms_scale, const float* __restrict__ w_down,
    const float* __restrict__ w_final, const float* __restrict__ b_final,
    float* __restrict__ d_out)
{
    __shared__ uint32_t As[MPTS * SA];   // feature chunk (tf32 bits); reused as h buffer
    __shared__ uint32_t Ws[KC * SA];     // (rms_scale * w_down) chunk (tf32 bits)
    __shared__ int      pidx[MPTS][16];
    __shared__ float    sumsq_s[MPTS];

    const int tid  = threadIdx.x;
    const int lane = tid & 31;
    const int warp = tid >> 5;
    const int p0   = blockIdx.x * MPTS;

    // ---- per-point index precompute --------------------------------------
    if (tid < MPTS) {
        int gp = p0 + tid;
        float px = d_pos[gp * 3 + 0];
        float py = d_pos[gp * 3 + 1];
        float pz = d_pos[gp * 3 + 2];
        pidx[tid][0]  = (int)(px * 127.0f);
        pidx[tid][1]  = (int)(py * 127.0f);
        pidx[tid][2]  = (int)(pz * 127.0f);
        pidx[tid][3]  = (int)(px * 63.0f);
        pidx[tid][4]  = (int)(py * 63.0f);
        pidx[tid][5]  = (int)(pz * 63.0f);
        pidx[tid][6]  = (int)(px * 31.0f);
        pidx[tid][7]  = (int)(py * 31.0f);
        pidx[tid][8]  = (int)(pz * 31.0f);
        pidx[tid][9]  = (int)(px * 15.0f);
        pidx[tid][10] = (int)(py * 15.0f);
        pidx[tid][11] = (int)(pz * 15.0f);
        float tv = d_t[gp];
        pidx[tid][12] = (int)(tv * 15.0f);
        pidx[tid][13] = (int)(tv * 63.0f);
        sumsq_s[tid]  = 0.f;
    }
    __syncthreads();

    // warp tiling: 4 m-tiles (16 rows) x 2 n-halves (32 cols)
    const int mbase = (warp >> 1) * 16;
    const int nbase = (warp & 1) * 32;

    float acc[4][4];
#pragma unroll
    for (int i = 0; i < 4; i++)
#pragma unroll
        for (int j = 0; j < 4; j++) acc[i][j] = 0.f;

    // ---- K loop ----------------------------------------------------------
    for (int ch = 0; ch < NCHUNK; ch++) {
        const int kb = ch * KC;

        // fill W chunk: Ws[kl][n] = tf32(rms_scale[k] * w_down[k][n])
#pragma unroll
        for (int i = tid; i < KC * 16; i += 256) {
            int kl = i >> 4;
            int n4 = (i & 15) << 2;
            int kg = kb + kl;
            uint4 u;
            if (kg < 12240) {
                float4 w = *reinterpret_cast<const float4*>(w_down + kg * 64 + n4);
                float s = rms_scale[kg];
                u.x = f2tf32(w.x * s); u.y = f2tf32(w.y * s);
                u.z = f2tf32(w.z * s); u.w = f2tf32(w.w * s);
            } else {
                u.x = u.y = u.z = u.w = 0u;
            }
            *reinterpret_cast<uint4*>(&Ws[kl * SA + n4]) = u;
        }

        // fill A chunk: As[p][kl] = tf32(relu(feature)), plus sumsq
#pragma unroll
        for (int i = tid; i < MPTS * 16; i += 256) {
            int p   = i >> 4;
            int kl4 = (i & 15) << 2;
            float4 v = gather4(kb + kl4, pidx[p], T0, T1, T2, T3, S1t, S2t, TF);
            v.x = fmaxf(v.x, 0.f); v.y = fmaxf(v.y, 0.f);
            v.z = fmaxf(v.z, 0.f); v.w = fmaxf(v.w, 0.f);
            float s2 = v.x * v.x + v.y * v.y + v.z * v.z + v.w * v.w;
            s2 += __shfl_xor_sync(0xffffffffu, s2, 1);
            s2 += __shfl_xor_sync(0xffffffffu, s2, 2);
            s2 += __shfl_xor_sync(0xffffffffu, s2, 4);
            s2 += __shfl_xor_sync(0xffffffffu, s2, 8);
            if ((lane & 15) == 0) atomicAdd(&sumsq_s[p], s2);
            uint4 u;
            u.x = f2tf32(v.x); u.y = f2tf32(v.y);
            u.z = f2tf32(v.z); u.w = f2tf32(v.w);
            *reinterpret_cast<uint4*>(&As[p * SA + kl4]) = u;
        }
        __syncthreads();

        // mma over the chunk
#pragma unroll
        for (int kk = 0; kk < KC; kk += 8) {
            int ra = (mbase + (lane >> 2)) * SA + kk + (lane & 3);
            uint32_t a0 = As[ra];
            uint32_t a2 = As[ra + 4];
            uint32_t a1 = As[ra + 8 * SA];
            uint32_t a3 = As[ra + 8 * SA + 4];
#pragma unroll
            for (int nt = 0; nt < 4; nt++) {
                int bcol = nbase + nt * 8 + (lane >> 2);
                uint32_t b0 = Ws[(kk + (lane & 3)) * SA + bcol];
                uint32_t b1 = Ws[(kk + 4 + (lane & 3)) * SA + bcol];
                mma8(acc[nt], a0, a1, a2, a3, b0, b1);
            }
        }
        __syncthreads();
    }

    // ---- epilogue: rmsnorm scale + relu, write h to smem ------------------
    {
        int row0 = mbase + (lane >> 2);
        float ss0 = sumsq_s[row0];
        float ss1 = sumsq_s[row0 + 8];
        float inv0 = 1.0f / (sqrtf(ss0 * (1.0f / 12240.0f)) + 1e-8f);
        float inv1 = 1.0f / (sqrtf(ss1 * (1.0f / 12240.0f)) + 1e-8f);
        float* Hf = reinterpret_cast<float*>(As);
#pragma unroll
        for (int nt = 0; nt < 4; nt++) {
            int col = nbase + nt * 8 + (lane & 3) * 2;
            Hf[row0 * SA + col]           = fmaxf(acc[nt][0] * inv0, 0.f);
            Hf[row0 * SA + col + 1]       = fmaxf(acc[nt][1] * inv0, 0.f);
            Hf[(row0 + 8) * SA + col]     = fmaxf(acc[nt][2] * inv1, 0.f);
            Hf[(row0 + 8) * SA + col + 1] = fmaxf(acc[nt][3] * inv1, 0.f);
        }
    }
    __syncthreads();

    // ---- final tiny layer + sigmoid --------------------------------------
    if (tid < MPTS) {
        int gp = p0 + tid;
        const float* Hf = reinterpret_cast<const float*>(As);
        float o0 = b_final[0], o1 = b_final[1], o2 = b_final[2], o3 = b_final[3];
#pragma unroll 8
        for (int i = 0; i < 64; i++) {
            float h = Hf[tid * SA + i];
            float4 wf = *reinterpret_cast<const float4*>(w_final + i * 4);
            o0 += h * wf.x; o1 += h * wf.y; o2 += h * wf.z; o3 += h * wf.w;
        }
#pragma unroll
        for (int c = 0; c < 3; c++) {
            float dv = d_dir[gp * 3 + c];
            float4 wf = *reinterpret_cast<const float4*>(w_final + (64 + c) * 4);
            o0 += dv * wf.x; o1 += dv * wf.y; o2 += dv * wf.z; o3 += dv * wf.w;
        }
        {
            float tv = d_t[gp];
            float4 wf = *reinterpret_cast<const float4*>(w_final + 67 * 4);
            o0 += tv * wf.x; o1 += tv * wf.y; o2 += tv * wf.z; o3 += tv * wf.w;
        }
        d_out[gp * 4 + 0] = 1.0f / (1.0f + expf(-o0));
        d_out[gp * 4 + 1] = 1.0f / (1.0f + expf(-o1));
        d_out[gp * 4 + 2] = 1.0f / (1.0f + expf(-o2));
        d_out[gp * 4 + 3] = 1.0f / (1.0f + expf(-o3));
    }
}

extern "C" void kernel_launch(void* const* d_in, const int* in_sizes, int n_in,
                              void* d_out, int out_size) {
    const float* pos       = (const float*)d_in[0];
    const float* dirv      = (const float*)d_in[1];
    const float* t         = (const float*)d_in[2];
    const float* table0    = (const float*)d_in[3];
    const float* table1    = (const float*)d_in[4];
    const float* table2    = (const float*)d_in[5];
    const float* table3    = (const float*)d_in[6];
    const float* st1       = (const float*)d_in[7];
    const float* st2       = (const float*)d_in[8];
    const float* tf3       = (const float*)d_in[9];
    const float* rms_scale = (const float*)d_in[10];
    const float* w_down    = (const float*)d_in[11];
    const float* w_final   = (const float*)d_in[12];
    const float* b_final   = (const float*)d_in[13];
    float* out = (float*)d_out;

    stlt_fused_kernel<<<8192 / MPTS, 256>>>(
        pos, dirv, t, table0, table1, table2, table3, st1, st2, tf3,
        rms_scale, w_down, w_final, b_final, out);
}

// round 2
// speedup vs baseline: 1.2118x; 1.2118x over previous
#include <cuda_runtime.h>
#include <cstdint>

// ---------------------------------------------------------------------------
// Round 2: software-pipelined fused kernel.
//   Kernel 1: Wt[k][n] = tf32(rms_scale[k] * w_down[k][n]) into __device__ buf.
//   Kernel 2: per CTA 16 points, K=12288 in 96 chunks of 128.
//     pipeline: [STS chunk ch] -> sync -> [LDG gather ch+1] [mma ch from smem A
//     + global Wt B]. One barrier per chunk, double-buffered A.
// ---------------------------------------------------------------------------

#define MPTS   16
#define TPB    128
#define KC     128
#define KPAD   12288
#define NCH    (KPAD / KC)
#define SA     132            // smem row stride (u32), KC + 4 pad

__device__ uint32_t g_Wt[KPAD * 64];   // tf32 bits, [k][n], zero-padded tail

__constant__ int c_OFF7[7][3] = {
    {0,0,0},{1,0,0},{-1,0,0},{0,1,0},{0,-1,0},{0,0,1},{0,0,-1}};
__constant__ int c_FACE[6][3] = {
    {1,0,0},{-1,0,0},{0,1,0},{0,-1,0},{0,0,1},{0,0,-1}};
__constant__ int c_CORNER[8][3] = {
    {1,1,1},{-1,-1,-1},{1,-1,-1},{-1,1,1},{1,1,-1},{-1,-1,1},{1,-1,1},{-1,1,-1}};
__constant__ int c_ETEMP[11] = {-64,-8,-4,-2,-1,0,1,2,4,8,64};

__device__ __forceinline__ uint32_t f2tf32(float x) {
    uint32_t u;
    asm("cvt.rna.tf32.f32 %0, %1;" : "=r"(u) : "f"(x));
    return u;
}

__device__ __forceinline__ void mma8(float* c,
                                     uint32_t a0, uint32_t a1, uint32_t a2, uint32_t a3,
                                     uint32_t b0, uint32_t b1) {
    asm("mma.sync.aligned.m16n8k8.row.col.f32.tf32.tf32.f32 "
        "{%0,%1,%2,%3}, {%4,%5,%6,%7}, {%8,%9}, {%0,%1,%2,%3};"
        : "+f"(c[0]), "+f"(c[1]), "+f"(c[2]), "+f"(c[3])
        : "r"(a0), "r"(a1), "r"(a2), "r"(a3), "r"(b0), "r"(b1));
}

// ---------------------------------------------------------------------------
// W precompute kernel
__global__ void __launch_bounds__(256)
wt_precompute_kernel(const float* __restrict__ w_down,
                     const float* __restrict__ rms_scale)
{
    int i = blockIdx.x * 256 + threadIdx.x;     // one float4 per thread
    if (i >= KPAD * 16) return;
    int k  = i >> 4;
    int n4 = (i & 15) << 2;
    uint4 u;
    if (k < 12240) {
        float4 w = *reinterpret_cast<const float4*>(w_down + k * 64 + n4);
        float s = rms_scale[k];
        u.x = f2tf32(w.x * s); u.y = f2tf32(w.y * s);
        u.z = f2tf32(w.z * s); u.w = f2tf32(w.w * s);
    } else {
        u.x = u.y = u.z = u.w = 0u;
    }
    reinterpret_cast<uint4*>(g_Wt)[i] = u;
}

// ---------------------------------------------------------------------------
// Gather 4 consecutive features [k, k+4). Segment map (all 4-aligned):
//   [0,112) T0 | [112,560) T1 | [560,2352) T2 | [2352,9520) T3
//   [9520,11312) st1 | [11312,11536) st2 | [11536,12240) tf3 | pad 0
__device__ __forceinline__ float4 gather4(
    int k, const int* __restrict__ pi,
    const float* __restrict__ T0, const float* __restrict__ T1,
    const float* __restrict__ T2, const float* __restrict__ T3,
    const float* __restrict__ S1t, const float* __restrict__ S2t,
    const float* __restrict__ TF)
{
    if (k < 9520) {
        const float* tab; int r, flog, dlog, ix, iy, iz;
        if (k < 112)       { tab = T0; r = k;        flog = 4;  dlog = 7; ix = pi[0]; iy = pi[1];  iz = pi[2];  }
        else if (k < 560)  { tab = T1; r = k - 112;  flog = 6;  dlog = 6; ix = pi[3]; iy = pi[4];  iz = pi[5];  }
        else if (k < 2352) { tab = T2; r = k - 560;  flog = 8;  dlog = 5; ix = pi[6]; iy = pi[7];  iz = pi[8];  }
        else               { tab = T3; r = k - 2352; flog = 10; dlog = 4; ix = pi[9]; iy = pi[10]; iz = pi[11]; }
        int o = r >> flog;
        int f = r & ((1 << flog) - 1);
        int d = 1 << dlog, m = d - 1;
        int cx = (ix + c_OFF7[o][0] + d) & m;
        int cy = (iy + c_OFF7[o][1] + d) & m;
        int cz = (iz + c_OFF7[o][2] + d) & m;
        int addr = (((((cx << dlog) | cy) << dlog) | cz) << flog) + f;
        return *reinterpret_cast<const float4*>(tab + addr);
    }
    if (k < 12240) {
        int tb = pi[12], tv = pi[13];
        if (k < 11536) {
            bool is1 = (k < 11312);
            int r, o, f;
            if (is1) { r = k - 9520;  o = r >> 6; f = r & 63; }
            else     { r = k - 11312; o = r >> 3; f = r & 7;  }
            int sx, sy, sz;
            if (o < 12) { int i = o >> 1;        sx = c_FACE[i][0];   sy = c_FACE[i][1];   sz = c_FACE[i][2];   }
            else        { int i = (o - 12) >> 1; sx = c_CORNER[i][0]; sy = c_CORNER[i][1]; sz = c_CORNER[i][2]; }
            int st = (o & 1) ? -1 : 1;
            if (is1) {   // (16,16,16,64) F=64
                int a  = (tb + sx + 16) & 15;
                int b  = (tb + sy + 16) & 15;
                int c  = (tb + sz + 16) & 15;
                int dd = (tv + st + 64) & 63;
                int addr = (((((((a << 4) | b) << 4) | c) << 6) | dd) << 6) + f;
                return *reinterpret_cast<const float4*>(S1t + addr);
            } else {     // (64,64,64,64) F=8
                int a  = (tb + sx + 64) & 63;
                int b  = (tb + sy + 64) & 63;
                int c  = (tb + sz + 64) & 63;
                int dd = (tv + st + 64) & 63;
                int addr = (((((((a << 6) | b) << 6) | c) << 6) | dd) << 3) + f;
                return *reinterpret_cast<const float4*>(S2t + addr);
            }
        } else {         // tf3 (4,4,4,65536) F=8
            int r = k - 11536;
            int o = r >> 3, f = r & 7;
            int ci = o / 11, ti = o - ci * 11;
            int sx = c_CORNER[ci][0], sy = c_CORNER[ci][1], sz = c_CORNER[ci][2];
            int st = c_ETEMP[ti];
            int a  = (tb + sx + 4) & 3;
            int b  = (tb + sy + 4) & 3;
            int c  = (tb + sz + 4) & 3;
            int dd = (tv + st + 65536) & 65535;
            int addr = (((((((a << 2) | b) << 2) | c) << 16) | dd) << 3) + f;
            return *reinterpret_cast<const float4*>(TF + addr);
        }
    }
    return make_float4(0.f, 0.f, 0.f, 0.f);
}

// ---------------------------------------------------------------------------
__global__ void __launch_bounds__(TPB, 4)
stlt_fused_kernel(
    const float* __restrict__ d_pos, const float* __restrict__ d_dir,
    const float* __restrict__ d_t,
    const float* __restrict__ T0, const float* __restrict__ T1,
    const float* __restrict__ T2, const float* __restrict__ T3,
    const float* __restrict__ S1t, const float* __restrict__ S2t,
    const float* __restrict__ TF,
    const float* __restrict__ w_final, const float* __restrict__ b_final,
    float* __restrict__ d_out)
{
    __shared__ uint32_t As[2 * MPTS * SA];   // double-buffered A chunk (tf32)
    __shared__ int      pidx[MPTS][16];
    __shared__ float    sumsq_s[MPTS];

    const int tid  = threadIdx.x;
    const int lane = tid & 31;
    const int warp = tid >> 5;
    const int p0   = blockIdx.x * MPTS;

    if (tid < MPTS) {
        int gp = p0 + tid;
        float px = d_pos[gp * 3 + 0];
        float py = d_pos[gp * 3 + 1];
        float pz = d_pos[gp * 3 + 2];
        pidx[tid][0]  = (int)(px * 127.0f);
        pidx[tid][1]  = (int)(py * 127.0f);
        pidx[tid][2]  = (int)(pz * 127.0f);
        pidx[tid][3]  = (int)(px * 63.0f);
        pidx[tid][4]  = (int)(py * 63.0f);
        pidx[tid][5]  = (int)(pz * 63.0f);
        pidx[tid][6]  = (int)(px * 31.0f);
        pidx[tid][7]  = (int)(py * 31.0f);
        pidx[tid][8]  = (int)(pz * 31.0f);
        pidx[tid][9]  = (int)(px * 15.0f);
        pidx[tid][10] = (int)(py * 15.0f);
        pidx[tid][11] = (int)(pz * 15.0f);
        float tv = d_t[gp];
        pidx[tid][12] = (int)(tv * 15.0f);
        pidx[tid][13] = (int)(tv * 63.0f);
        sumsq_s[tid]  = 0.f;
    }
    __syncthreads();

    // warp w covers all 16 rows x cols [w*16, w*16+16)
    const int nbase = warp * 16;
    float acc[2][4];
#pragma unroll
    for (int i = 0; i < 2; i++)
#pragma unroll
        for (int j = 0; j < 4; j++) acc[i][j] = 0.f;

    // prologue: gather chunk 0 into regs (4 float4 per thread)
    float4 v[4];
#pragma unroll
    for (int j = 0; j < 4; j++) {
        int i  = tid + j * TPB;
        int p  = i >> 5;
        int k4 = (i & 31) << 2;
        v[j] = gather4(k4, pidx[p], T0, T1, T2, T3, S1t, S2t, TF);
    }

    for (int ch = 0; ch < NCH; ch++) {
        uint32_t* buf = As + (ch & 1) * (MPTS * SA);
        const int kb  = ch * KC;

        // ---- STS phase: relu + sumsq + cvt + store current chunk ----------
#pragma unroll
        for (int j = 0; j < 4; j++) {
            int i  = tid + j * TPB;
            int p  = i >> 5;          // whole warp on one point
            int k4 = (i & 31) << 2;
            float4 w = v[j];
            w.x = fmaxf(w.x, 0.f); w.y = fmaxf(w.y, 0.f);
            w.z = fmaxf(w.z, 0.f); w.w = fmaxf(w.w, 0.f);
            float s2 = w.x * w.x + w.y * w.y + w.z * w.z + w.w * w.w;
            s2 += __shfl_xor_sync(0xffffffffu, s2, 1);
            s2 += __shfl_xor_sync(0xffffffffu, s2, 2);
            s2 += __shfl_xor_sync(0xffffffffu, s2, 4);
            s2 += __shfl_xor_sync(0xffffffffu, s2, 8);
            s2 += __shfl_xor_sync(0xffffffffu, s2, 16);
            if (lane == 0) atomicAdd(&sumsq_s[p], s2);
            uint4 u;
            u.x = f2tf32(w.x); u.y = f2tf32(w.y);
            u.z = f2tf32(w.z); u.w = f2tf32(w.w);
            *reinterpret_cast<uint4*>(&buf[p * SA + k4]) = u;
        }
        __syncthreads();

        // ---- prefetch next chunk (LDGs overlap the mma below) -------------
        if (ch + 1 < NCH) {
#pragma unroll
            for (int j = 0; j < 4; j++) {
                int i  = tid + j * TPB;
                int p  = i >> 5;
                int k4 = (i & 31) << 2;
                v[j] = gather4(kb + KC + k4, pidx[p], T0, T1, T2, T3, S1t, S2t, TF);
            }
        }

        // ---- mma phase ----------------------------------------------------
        const uint32_t* Wb = g_Wt + kb * 64;
#pragma unroll
        for (int kk = 0; kk < KC; kk += 8) {
            int ra = (lane >> 2) * SA + kk + (lane & 3);
            uint32_t a0 = buf[ra];
            uint32_t a1 = buf[ra + 8 * SA];
            uint32_t a2 = buf[ra + 4];
            uint32_t a3 = buf[ra + 8 * SA + 4];
#pragma unroll
            for (int nt = 0; nt < 2; nt++) {
                int col = nbase + nt * 8 + (lane >> 2);
                uint32_t b0 = Wb[(kk + (lane & 3)) * 64 + col];
                uint32_t b1 = Wb[(kk + 4 + (lane & 3)) * 64 + col];
                mma8(acc[nt], a0, a1, a2, a3, b0, b1);
            }
        }
    }

    // ---- epilogue: rmsnorm + relu -> h in smem (reuse As buf0) ------------
    {
        int row0 = lane >> 2;
        float ss0 = sumsq_s[row0];
        float ss1 = sumsq_s[row0 + 8];
        float inv0 = 1.0f / (sqrtf(ss0 * (1.0f / 12240.0f)) + 1e-8f);
        float inv1 = 1.0f / (sqrtf(ss1 * (1.0f / 12240.0f)) + 1e-8f);
        float* Hf = reinterpret_cast<float*>(As);
#pragma unroll
        for (int nt = 0; nt < 2; nt++) {
            int col = nbase + nt * 8 + (lane & 3) * 2;
            Hf[row0 * SA + col]           = fmaxf(acc[nt][0] * inv0, 0.f);
            Hf[row0 * SA + col + 1]       = fmaxf(acc[nt][1] * inv0, 0.f);
            Hf[(row0 + 8) * SA + col]     = fmaxf(acc[nt][2] * inv1, 0.f);
            Hf[(row0 + 8) * SA + col + 1] = fmaxf(acc[nt][3] * inv1, 0.f);
        }
    }
    __syncthreads();

    // ---- final tiny layer + sigmoid ---------------------------------------
    if (tid < MPTS) {
        int gp = p0 + tid;
        const float* Hf = reinterpret_cast<const float*>(As);
        float o0 = b_final[0], o1 = b_final[1], o2 = b_final[2], o3 = b_final[3];
#pragma unroll 8
        for (int i = 0; i < 64; i++) {
            float h = Hf[tid * SA + i];
            float4 wf = *reinterpret_cast<const float4*>(w_final + i * 4);
            o0 += h * wf.x; o1 += h * wf.y; o2 += h * wf.z; o3 += h * wf.w;
        }
#pragma unroll
        for (int c = 0; c < 3; c++) {
            float dv = d_dir[gp * 3 + c];
            float4 wf = *reinterpret_cast<const float4*>(w_final + (64 + c) * 4);
            o0 += dv * wf.x; o1 += dv * wf.y; o2 += dv * wf.z; o3 += dv * wf.w;
        }
        {
            float tv = d_t[gp];
            float4 wf = *reinterpret_cast<const float4*>(w_final + 67 * 4);
            o0 += tv * wf.x; o1 += tv * wf.y; o2 += tv * wf.z; o3 += tv * wf.w;
        }
        d_out[gp * 4 + 0] = 1.0f / (1.0f + expf(-o0));
        d_out[gp * 4 + 1] = 1.0f / (1.0f + expf(-o1));
        d_out[gp * 4 + 2] = 1.0f / (1.0f + expf(-o2));
        d_out[gp * 4 + 3] = 1.0f / (1.0f + expf(-o3));
    }
}

extern "C" void kernel_launch(void* const* d_in, const int* in_sizes, int n_in,
                              void* d_out, int out_size) {
    const float* pos       = (const float*)d_in[0];
    const float* dirv      = (const float*)d_in[1];
    const float* t         = (const float*)d_in[2];
    const float* table0    = (const float*)d_in[3];
    const float* table1    = (const float*)d_in[4];
    const float* table2    = (const float*)d_in[5];
    const float* table3    = (const float*)d_in[6];
    const float* st1       = (const float*)d_in[7];
    const float* st2       = (const float*)d_in[8];
    const float* tf3       = (const float*)d_in[9];
    const float* rms_scale = (const float*)d_in[10];
    const float* w_down    = (const float*)d_in[11];
    const float* w_final   = (const float*)d_in[12];
    const float* b_final   = (const float*)d_in[13];
    float* out = (float*)d_out;

    wt_precompute_kernel<<<(KPAD * 16 + 255) / 256, 256>>>(w_down, rms_scale);
    stlt_fused_kernel<<<8192 / MPTS, TPB>>>(
        pos, dirv, t, table0, table1, table2, table3, st1, st2, tf3,
        w_final, b_final, out);
}

// round 4
// speedup vs baseline: 3.2124x; 2.6510x over previous
#include <cuda_runtime.h>
#include <cstdint>

// ---------------------------------------------------------------------------
// Round 3: L1-wavefront diet.
//   - g_Wf: B fragments stored fragment-major (uint2 per lane) -> 1 coalesced
//     LDG.64 per (k8, ntile) per warp.
//   - A fragments via ldmatrix.x4 (1 LDSM replaces 4 LDS.32).
//   - Warps split 2x2: nhalf = warp>>1, khalf = warp&1. Cross-k reduction in
//     smem at the end.
// ---------------------------------------------------------------------------

#define MPTS   16
#define TPB    128
#define KC     128
#define KPAD   12288
#define NCH    (KPAD / KC)
#define SA     132            // A smem row stride (u32)
#define RS     72             // reduce buffer row stride (floats)
#define NK8    (KPAD / 8)     // 1536 global k8 groups

__device__ uint2 g_Wf[NK8 * 8 * 32];   // [(k8*8 + ntile)*32 + lane] = {b0,b1}

__constant__ int c_OFF7[7][3] = {
    {0,0,0},{1,0,0},{-1,0,0},{0,1,0},{0,-1,0},{0,0,1},{0,0,-1}};
__constant__ int c_FACE[6][3] = {
    {1,0,0},{-1,0,0},{0,1,0},{0,-1,0},{0,0,1},{0,0,-1}};
__constant__ int c_CORNER[8][3] = {
    {1,1,1},{-1,-1,-1},{1,-1,-1},{-1,1,1},{1,1,-1},{-1,-1,1},{1,-1,1},{-1,1,-1}};
__constant__ int c_ETEMP[11] = {-64,-8,-4,-2,-1,0,1,2,4,8,64};

__device__ __forceinline__ uint32_t f2tf32(float x) {
    uint32_t u;
    asm("cvt.rna.tf32.f32 %0, %1;" : "=r"(u) : "f"(x));
    return u;
}

__device__ __forceinline__ uint32_t s2u(const void* p) {
    uint32_t a;
    asm("{ .reg .u64 t; cvta.to.shared.u64 t, %1; cvt.u32.u64 %0, t; }"
        : "=r"(a) : "l"(p));
    return a;
}

__device__ __forceinline__ void mma8(float* c,
                                     uint32_t a0, uint32_t a1, uint32_t a2, uint32_t a3,
                                     uint32_t b0, uint32_t b1) {
    asm("mma.sync.aligned.m16n8k8.row.col.f32.tf32.tf32.f32 "
        "{%0,%1,%2,%3}, {%4,%5,%6,%7}, {%8,%9}, {%0,%1,%2,%3};"
        : "+f"(c[0]), "+f"(c[1]), "+f"(c[2]), "+f"(c[3])
        : "r"(a0), "r"(a1), "r"(a2), "r"(a3), "r"(b0), "r"(b1));
}

// ---------------------------------------------------------------------------
// W fragment precompute: one thread per (k8, ntile, lane).
__global__ void __launch_bounds__(256)
wf_precompute_kernel(const float* __restrict__ w_down,
                     const float* __restrict__ rms_scale)
{
    int T = blockIdx.x * 256 + threadIdx.x;
    if (T >= NK8 * 8 * 32) return;
    int lane = T & 31;
    int nt   = (T >> 5) & 7;
    int K8   = T >> 8;
    int n  = nt * 8 + (lane >> 2);
    int k0 = K8 * 8 + (lane & 3);
    int k1 = k0 + 4;
    uint2 u;
    u.x = (k0 < 12240) ? f2tf32(w_down[k0 * 64 + n] * rms_scale[k0]) : 0u;
    u.y = (k1 < 12240) ? f2tf32(w_down[k1 * 64 + n] * rms_scale[k1]) : 0u;
    g_Wf[T] = u;
}

// ---------------------------------------------------------------------------
// Gather 4 consecutive features [k, k+4). Segment map (all 4-aligned):
//   [0,112) T0 | [112,560) T1 | [560,2352) T2 | [2352,9520) T3
//   [9520,11312) st1 | [11312,11536) st2 | [11536,12240) tf3 | pad 0
__device__ __forceinline__ float4 gather4(
    int k, const int* __restrict__ pi,
    const float* __restrict__ T0, const float* __restrict__ T1,
    const float* __restrict__ T2, const float* __restrict__ T3,
    const float* __restrict__ S1t, const float* __restrict__ S2t,
    const float* __restrict__ TF)
{
    if (k < 9520) {
        const float* tab; int r, flog, dlog, ix, iy, iz;
        if (k < 112)       { tab = T0; r = k;        flog = 4;  dlog = 7; ix = pi[0]; iy = pi[1];  iz = pi[2];  }
        else if (k < 560)  { tab = T1; r = k - 112;  flog = 6;  dlog = 6; ix = pi[3]; iy = pi[4];  iz = pi[5];  }
        else if (k < 2352) { tab = T2; r = k - 560;  flog = 8;  dlog = 5; ix = pi[6]; iy = pi[7];  iz = pi[8];  }
        else               { tab = T3; r = k - 2352; flog = 10; dlog = 4; ix = pi[9]; iy = pi[10]; iz = pi[11]; }
        int o = r >> flog;
        int f = r & ((1 << flog) - 1);
        int d = 1 << dlog, m = d - 1;
        int cx = (ix + c_OFF7[o][0] + d) & m;
        int cy = (iy + c_OFF7[o][1] + d) & m;
        int cz = (iz + c_OFF7[o][2] + d) & m;
        int addr = (((((cx << dlog) | cy) << dlog) | cz) << flog) + f;
        return *reinterpret_cast<const float4*>(tab + addr);
    }
    if (k < 12240) {
        int tb = pi[12], tv = pi[13];
        if (k < 11536) {
            bool is1 = (k < 11312);
            int r, o, f;
            if (is1) { r = k - 9520;  o = r >> 6; f = r & 63; }
            else     { r = k - 11312; o = r >> 3; f = r & 7;  }
            int sx, sy, sz;
            if (o < 12) { int i = o >> 1;        sx = c_FACE[i][0];   sy = c_FACE[i][1];   sz = c_FACE[i][2];   }
            else        { int i = (o - 12) >> 1; sx = c_CORNER[i][0]; sy = c_CORNER[i][1]; sz = c_CORNER[i][2]; }
            int st = (o & 1) ? -1 : 1;
            if (is1) {
                int a  = (tb + sx + 16) & 15;
                int b  = (tb + sy + 16) & 15;
                int c  = (tb + sz + 16) & 15;
                int dd = (tv + st + 64) & 63;
                int addr = (((((((a << 4) | b) << 4) | c) << 6) | dd) << 6) + f;
                return *reinterpret_cast<const float4*>(S1t + addr);
            } else {
                int a  = (tb + sx + 64) & 63;
                int b  = (tb + sy + 64) & 63;
                int c  = (tb + sz + 64) & 63;
                int dd = (tv + st + 64) & 63;
                int addr = (((((((a << 6) | b) << 6) | c) << 6) | dd) << 3) + f;
                return *reinterpret_cast<const float4*>(S2t + addr);
            }
        } else {
            int r = k - 11536;
            int o = r >> 3, f = r & 7;
            int ci = o / 11, ti = o - ci * 11;
            int sx = c_CORNER[ci][0], sy = c_CORNER[ci][1], sz = c_CORNER[ci][2];
            int st = c_ETEMP[ti];
            int a  = (tb + sx + 4) & 3;
            int b  = (tb + sy + 4) & 3;
            int c  = (tb + sz + 4) & 3;
            int dd = (tv + st + 65536) & 65535;
            int addr = (((((((a << 2) | b) << 2) | c) << 16) | dd) << 3) + f;
            return *reinterpret_cast<const float4*>(TF + addr);
        }
    }
    return make_float4(0.f, 0.f, 0.f, 0.f);
}

// ---------------------------------------------------------------------------
__global__ void __launch_bounds__(TPB, 4)
stlt_fused_kernel(
    const float* __restrict__ d_pos, const float* __restrict__ d_dir,
    const float* __restrict__ d_t,
    const float* __restrict__ T0, const float* __restrict__ T1,
    const float* __restrict__ T2, const float* __restrict__ T3,
    const float* __restrict__ S1t, const float* __restrict__ S2t,
    const float* __restrict__ TF,
    const float* __restrict__ w_final, const float* __restrict__ b_final,
    float* __restrict__ d_out)
{
    __shared__ uint32_t As[2 * MPTS * SA];   // double-buffered A chunk (tf32)
    __shared__ float    Rbuf[MPTS * RS];     // cross-k reduce + h buffer
    __shared__ int      pidx[MPTS][16];
    __shared__ float    sumsq_s[MPTS];

    const int tid  = threadIdx.x;
    const int lane = tid & 31;
    const int warp = tid >> 5;
    const int nhalf = warp >> 1;   // n cols [nhalf*32, +32)
    const int khalf = warp & 1;    // k subrange within chunk
    const int p0   = blockIdx.x * MPTS;

    if (tid < MPTS) {
        int gp = p0 + tid;
        float px = d_pos[gp * 3 + 0];
        float py = d_pos[gp * 3 + 1];
        float pz = d_pos[gp * 3 + 2];
        pidx[tid][0]  = (int)(px * 127.0f);
        pidx[tid][1]  = (int)(py * 127.0f);
        pidx[tid][2]  = (int)(pz * 127.0f);
        pidx[tid][3]  = (int)(px * 63.0f);
        pidx[tid][4]  = (int)(py * 63.0f);
        pidx[tid][5]  = (int)(pz * 63.0f);
        pidx[tid][6]  = (int)(px * 31.0f);
        pidx[tid][7]  = (int)(py * 31.0f);
        pidx[tid][8]  = (int)(pz * 31.0f);
        pidx[tid][9]  = (int)(px * 15.0f);
        pidx[tid][10] = (int)(py * 15.0f);
        pidx[tid][11] = (int)(pz * 15.0f);
        float tv = d_t[gp];
        pidx[tid][12] = (int)(tv * 15.0f);
        pidx[tid][13] = (int)(tv * 63.0f);
        sumsq_s[tid]  = 0.f;
    }
    __syncthreads();

    float acc[4][4];
#pragma unroll
    for (int i = 0; i < 4; i++)
#pragma unroll
        for (int j = 0; j < 4; j++) acc[i][j] = 0.f;

    // ldmatrix source address (lane-dependent), relative to chunk buffer:
    //   tile = lane>>3 : 0 -> rows0-7 k+0 | 1 -> rows8-15 k+0 | 2 -> rows0-7 k+4 | 3 -> rows8-15 k+4
    const int lm_row = ((lane >> 3) & 1) * 8 + (lane & 7);
    const int lm_kof = (lane >> 4) * 4;

    // prologue: gather chunk 0 into regs (4 float4 per thread)
    float4 v[4];
#pragma unroll
    for (int j = 0; j < 4; j++) {
        int i  = tid + j * TPB;
        int p  = i >> 5;
        int k4 = (i & 31) << 2;
        v[j] = gather4(k4, pidx[p], T0, T1, T2, T3, S1t, S2t, TF);
    }

    for (int ch = 0; ch < NCH; ch++) {
        uint32_t* buf = As + (ch & 1) * (MPTS * SA);
        const int kb  = ch * KC;

        // ---- STS phase: relu + sumsq + cvt + store current chunk ----------
#pragma unroll
        for (int j = 0; j < 4; j++) {
            int i  = tid + j * TPB;
            int p  = i >> 5;
            int k4 = (i & 31) << 2;
            float4 w = v[j];
            w.x = fmaxf(w.x, 0.f); w.y = fmaxf(w.y, 0.f);
            w.z = fmaxf(w.z, 0.f); w.w = fmaxf(w.w, 0.f);
            float s2 = w.x * w.x + w.y * w.y + w.z * w.z + w.w * w.w;
            s2 += __shfl_xor_sync(0xffffffffu, s2, 1);
            s2 += __shfl_xor_sync(0xffffffffu, s2, 2);
            s2 += __shfl_xor_sync(0xffffffffu, s2, 4);
            s2 += __shfl_xor_sync(0xffffffffu, s2, 8);
            s2 += __shfl_xor_sync(0xffffffffu, s2, 16);
            if (lane == 0) atomicAdd(&sumsq_s[p], s2);
            uint4 u;
            u.x = f2tf32(w.x); u.y = f2tf32(w.y);
            u.z = f2tf32(w.z); u.w = f2tf32(w.w);
            *reinterpret_cast<uint4*>(&buf[p * SA + k4]) = u;
        }
        __syncthreads();

        // ---- prefetch next chunk (LDGs overlap the mma below) -------------
        if (ch + 1 < NCH) {
#pragma unroll
            for (int j = 0; j < 4; j++) {
                int i  = tid + j * TPB;
                int p  = i >> 5;
                int k4 = (i & 31) << 2;
                v[j] = gather4(kb + KC + k4, pidx[p], T0, T1, T2, T3, S1t, S2t, TF);
            }
        }

        // ---- mma phase: this warp covers k8 in [khalf*8, +8), n [nhalf*32,+32)
        const uint2* Wp0 = g_Wf + ((((size_t)(ch * 16 + khalf * 8)) * 8 + nhalf * 4) << 5) + lane;
#pragma unroll
        for (int k8 = 0; k8 < 8; k8++) {
            int kk = (khalf * 8 + k8) * 8;
            uint32_t a0, a1, a2, a3;
            uint32_t addr = s2u(&buf[lm_row * SA + kk + lm_kof]);
            asm volatile("ldmatrix.sync.aligned.m8n8.x4.shared.b16 {%0,%1,%2,%3}, [%4];"
                         : "=r"(a0), "=r"(a1), "=r"(a2), "=r"(a3) : "r"(addr));
            const uint2* Wk = Wp0 + (size_t)k8 * 256;
#pragma unroll
            for (int nt = 0; nt < 4; nt++) {
                uint2 b = Wk[nt * 32];
                mma8(acc[nt], a0, a1, a2, a3, b.x, b.y);
            }
        }
    }

    // ---- cross-k reduction + rmsnorm + relu -> h in Rbuf ------------------
    {
        int row = lane >> 2;
        int cb  = nhalf * 32 + (lane & 3) * 2;
        if (khalf == 1) {
#pragma unroll
            for (int nt = 0; nt < 4; nt++) {
                int col = cb + nt * 8;
                Rbuf[row * RS + col]           = acc[nt][0];
                Rbuf[row * RS + col + 1]       = acc[nt][1];
                Rbuf[(row + 8) * RS + col]     = acc[nt][2];
                Rbuf[(row + 8) * RS + col + 1] = acc[nt][3];
            }
        }
        __syncthreads();
        if (khalf == 0) {
            float ss0 = sumsq_s[row];
            float ss1 = sumsq_s[row + 8];
            float inv0 = 1.0f / (sqrtf(ss0 * (1.0f / 12240.0f)) + 1e-8f);
            float inv1 = 1.0f / (sqrtf(ss1 * (1.0f / 12240.0f)) + 1e-8f);
#pragma unroll
            for (int nt = 0; nt < 4; nt++) {
                int col = cb + nt * 8;
                Rbuf[row * RS + col]           = fmaxf((acc[nt][0] + Rbuf[row * RS + col]) * inv0, 0.f);
                Rbuf[row * RS + col + 1]       = fmaxf((acc[nt][1] + Rbuf[row * RS + col + 1]) * inv0, 0.f);
                Rbuf[(row + 8) * RS + col]     = fmaxf((acc[nt][2] + Rbuf[(row + 8) * RS + col]) * inv1, 0.f);
                Rbuf[(row + 8) * RS + col + 1] = fmaxf((acc[nt][3] + Rbuf[(row + 8) * RS + col + 1]) * inv1, 0.f);
            }
        }
    }
    __syncthreads();

    // ---- final tiny layer + sigmoid ---------------------------------------
    if (tid < MPTS) {
        int gp = p0 + tid;
        float o0 = b_final[0], o1 = b_final[1], o2 = b_final[2], o3 = b_final[3];
#pragma unroll 8
        for (int i = 0; i < 64; i++) {
            float h = Rbuf[tid * RS + i];
            float4 wf = *reinterpret_cast<const float4*>(w_final + i * 4);
            o0 += h * wf.x; o1 += h * wf.y; o2 += h * wf.z; o3 += h * wf.w;
        }
#pragma unroll
        for (int c = 0; c < 3; c++) {
            float dv = d_dir[gp * 3 + c];
            float4 wf = *reinterpret_cast<const float4*>(w_final + (64 + c) * 4);
            o0 += dv * wf.x; o1 += dv * wf.y; o2 += dv * wf.z; o3 += dv * wf.w;
        }
        {
            float tv = d_t[gp];
            float4 wf = *reinterpret_cast<const float4*>(w_final + 67 * 4);
            o0 += tv * wf.x; o1 += tv * wf.y; o2 += tv * wf.z; o3 += tv * wf.w;
        }
        d_out[gp * 4 + 0] = 1.0f / (1.0f + expf(-o0));
        d_out[gp * 4 + 1] = 1.0f / (1.0f + expf(-o1));
        d_out[gp * 4 + 2] = 1.0f / (1.0f + expf(-o2));
        d_out[gp * 4 + 3] = 1.0f / (1.0f + expf(-o3));
    }
}

extern "C" void kernel_launch(void* const* d_in, const int* in_sizes, int n_in,
                              void* d_out, int out_size) {
    const float* pos       = (const float*)d_in[0];
    const float* dirv      = (const float*)d_in[1];
    const float* t         = (const float*)d_in[2];
    const float* table0    = (const float*)d_in[3];
    const float* table1    = (const float*)d_in[4];
    const float* table2    = (const float*)d_in[5];
    const float* table3    = (const float*)d_in[6];
    const float* st1       = (const float*)d_in[7];
    const float* st2       = (const float*)d_in[8];
    const float* tf3       = (const float*)d_in[9];
    const float* rms_scale = (const float*)d_in[10];
    const float* w_down    = (const float*)d_in[11];
    const float* w_final   = (const float*)d_in[12];
    const float* b_final   = (const float*)d_in[13];
    float* out = (float*)d_out;

    wf_precompute_kernel<<<(NK8 * 8 * 32 + 255) / 256, 256>>>(w_down, rms_scale);
    stlt_fused_kernel<<<8192 / MPTS, TPB>>>(
        pos, dirv, t, table0, table1, table2, table3, st1, st2, tf3,
        w_final, b_final, out);
}

// round 7
// speedup vs baseline: 3.6185x; 1.1264x over previous
#include <cuda_runtime.h>
#include <cstdint>

// ---------------------------------------------------------------------------
// Round 6: R4 wins without cp.async (bisect the misaligned fault).
//   Staging: proven LDG.128->reg->STS.128 double buffer (R3 path).
//   Kept: per-point base table, post-ldmatrix relu/cvt/sumsq, uint4 B frags.
//   Layout: TPB=256, 8 warps = 4 k-quarters x 2 n-halves, acc 4x4.
// ---------------------------------------------------------------------------

#define MPTS   16
#define TPB    256
#define KC     128
#define KPAD   12288
#define NCH    (KPAD / KC)
#define SA     132            // A smem row stride (u32)
#define RS     72             // reduce buffer row stride (floats)
#define NK8    (KPAD / 8)     // 1536
#define NB     172            // base-table entries per point

__device__ uint4 g_Wf4[NK8 * 4 * 32];  // [(K8*4 + nt2)*32 + lane] = {b0e,b1e,b0o,b1o}

__constant__ int c_OFF7[7][3] = {
    {0,0,0},{1,0,0},{-1,0,0},{0,1,0},{0,-1,0},{0,0,1},{0,0,-1}};
__constant__ int c_S14[14][3] = {
    {1,0,0},{-1,0,0},{0,1,0},{0,-1,0},{0,0,1},{0,0,-1},
    {1,1,1},{-1,-1,-1},{1,-1,-1},{-1,1,1},{1,1,-1},{-1,-1,1},{1,-1,1},{-1,1,-1}};
__constant__ int c_CORNER[8][3] = {
    {1,1,1},{-1,-1,-1},{1,-1,-1},{-1,1,1},{1,1,-1},{-1,-1,1},{1,-1,1},{-1,1,-1}};
__constant__ int c_ETEMP[11] = {-64,-8,-4,-2,-1,0,1,2,4,8,64};

__device__ __forceinline__ uint32_t f2tf32(float x) {
    uint32_t u;
    asm("cvt.rna.tf32.f32 %0, %1;" : "=r"(u) : "f"(x));
    return u;
}

__device__ __forceinline__ uint32_t s2u(const void* p) {
    uint32_t a;
    asm("{ .reg .u64 t; cvta.to.shared.u64 t, %1; cvt.u32.u64 %0, t; }"
        : "=r"(a) : "l"(p));
    return a;
}

__device__ __forceinline__ void mma8(float* c,
                                     uint32_t a0, uint32_t a1, uint32_t a2, uint32_t a3,
                                     uint32_t b0, uint32_t b1) {
    asm("mma.sync.aligned.m16n8k8.row.col.f32.tf32.tf32.f32 "
        "{%0,%1,%2,%3}, {%4,%5,%6,%7}, {%8,%9}, {%0,%1,%2,%3};"
        : "+f"(c[0]), "+f"(c[1]), "+f"(c[2]), "+f"(c[3])
        : "r"(a0), "r"(a1), "r"(a2), "r"(a3), "r"(b0), "r"(b1));
}

// ---------------------------------------------------------------------------
__global__ void __launch_bounds__(256)
wf_precompute_kernel(const float* __restrict__ w_down,
                     const float* __restrict__ rms_scale)
{
    int T = blockIdx.x * 256 + threadIdx.x;
    if (T >= NK8 * 4 * 32) return;
    int lane = T & 31;
    int nt2  = (T >> 5) & 3;
    int K8   = T >> 7;
    int ne = nt2 * 16 + (lane >> 2);
    int no = ne + 8;
    int k0 = K8 * 8 + (lane & 3);
    int k1 = k0 + 4;
    uint4 u;
    u.x = (k0 < 12240) ? f2tf32(w_down[k0 * 64 + ne] * rms_scale[k0]) : 0u;
    u.y = (k1 < 12240) ? f2tf32(w_down[k1 * 64 + ne] * rms_scale[k1]) : 0u;
    u.z = (k0 < 12240) ? f2tf32(w_down[k0 * 64 + no] * rms_scale[k0]) : 0u;
    u.w = (k1 < 12240) ? f2tf32(w_down[k1 * 64 + no] * rms_scale[k1]) : 0u;
    g_Wf4[T] = u;
}

// ---------------------------------------------------------------------------
// Gather 4 consecutive features via precomputed per-point base table.
__device__ __forceinline__ float4 gather4b(
    int k, const int* __restrict__ bp,
    const float* __restrict__ T0, const float* __restrict__ T1,
    const float* __restrict__ T2, const float* __restrict__ T3,
    const float* __restrict__ S1t, const float* __restrict__ S2t,
    const float* __restrict__ TF)
{
    if (k < 9520) {
        const float* tab; int r, flog, bi;
        if (k < 112)       { tab = T0; r = k;        flog = 4;  bi = 0;  }
        else if (k < 560)  { tab = T1; r = k - 112;  flog = 6;  bi = 7;  }
        else if (k < 2352) { tab = T2; r = k - 560;  flog = 8;  bi = 14; }
        else               { tab = T3; r = k - 2352; flog = 10; bi = 21; }
        int o = r >> flog;
        int f = r & ((1 << flog) - 1);
        return *reinterpret_cast<const float4*>(tab + bp[bi + o] + f);
    }
    if (k < 11312) {
        int r = k - 9520;
        return *reinterpret_cast<const float4*>(S1t + bp[28 + (r >> 6)] + (r & 63));
    }
    if (k < 11536) {
        int r = k - 11312;
        return *reinterpret_cast<const float4*>(S2t + bp[56 + (r >> 3)] + (r & 7));
    }
    if (k < 12240) {
        int r = k - 11536;
        return *reinterpret_cast<const float4*>(TF + bp[84 + (r >> 3)] + (r & 7));
    }
    return make_float4(0.f, 0.f, 0.f, 0.f);
}

// ---------------------------------------------------------------------------
__global__ void __launch_bounds__(TPB, 2)
stlt_fused_kernel(
    const float* __restrict__ d_pos, const float* __restrict__ d_dir,
    const float* __restrict__ d_t,
    const float* __restrict__ T0, const float* __restrict__ T1,
    const float* __restrict__ T2, const float* __restrict__ T3,
    const float* __restrict__ S1t, const float* __restrict__ S2t,
    const float* __restrict__ TF,
    const float* __restrict__ w_final, const float* __restrict__ b_final,
    float* __restrict__ d_out)
{
    __shared__ alignas(16) uint32_t As[2 * MPTS * SA];   // double-buffered A
    __shared__ alignas(16) float    Rbuf[MPTS * RS];
    __shared__ int      bases[MPTS * NB];
    __shared__ int      pidx[MPTS][14];
    __shared__ float    sumsq_s[MPTS];

    const int tid  = threadIdx.x;
    const int lane = tid & 31;
    const int warp = tid >> 5;
    const int kq   = warp >> 1;     // k-quarter 0..3
    const int nh   = warp & 1;      // n-half 0..1 (cols [nh*32, +32))
    const int p0   = blockIdx.x * MPTS;

    if (tid < MPTS) {
        int gp = p0 + tid;
        float px = d_pos[gp * 3 + 0];
        float py = d_pos[gp * 3 + 1];
        float pz = d_pos[gp * 3 + 2];
        pidx[tid][0]  = (int)(px * 127.0f);
        pidx[tid][1]  = (int)(py * 127.0f);
        pidx[tid][2]  = (int)(pz * 127.0f);
        pidx[tid][3]  = (int)(px * 63.0f);
        pidx[tid][4]  = (int)(py * 63.0f);
        pidx[tid][5]  = (int)(pz * 63.0f);
        pidx[tid][6]  = (int)(px * 31.0f);
        pidx[tid][7]  = (int)(py * 31.0f);
        pidx[tid][8]  = (int)(pz * 31.0f);
        pidx[tid][9]  = (int)(px * 15.0f);
        pidx[tid][10] = (int)(py * 15.0f);
        pidx[tid][11] = (int)(pz * 15.0f);
        float tv = d_t[gp];
        pidx[tid][12] = (int)(tv * 15.0f);
        pidx[tid][13] = (int)(tv * 63.0f);
        sumsq_s[tid]  = 0.f;
    }
    __syncthreads();

    // ---- fill per-point base-address table (element offsets) --------------
    for (int e = tid; e < MPTS * NB; e += TPB) {
        int p = e / NB;
        int j = e - p * NB;
        int b;
        if (j < 28) {                       // spatial: tau = j/7, o = j%7
            int tau  = j / 7;
            int o    = j - tau * 7;
            int dlog = 7 - tau;
            int flog = 4 + 2 * tau;
            int d = 1 << dlog, m = d - 1;
            int cx = (pidx[p][tau * 3 + 0] + c_OFF7[o][0] + d) & m;
            int cy = (pidx[p][tau * 3 + 1] + c_OFF7[o][1] + d) & m;
            int cz = (pidx[p][tau * 3 + 2] + c_OFF7[o][2] + d) & m;
            b = ((((cx << dlog) | cy) << dlog) | cz) << flog;
        } else if (j < 56) {                // st1 (16,16,16,64) F=64
            int jj = j - 28;
            int si = jj >> 1;
            int tt = (jj & 1) ? -1 : 1;
            int tb = pidx[p][12], tv = pidx[p][13];
            int a  = (tb + c_S14[si][0] + 16) & 15;
            int bb = (tb + c_S14[si][1] + 16) & 15;
            int c  = (tb + c_S14[si][2] + 16) & 15;
            int dd = (tv + tt + 64) & 63;
            b = ((((((a << 4) | bb) << 4) | c) << 6) | dd) << 6;
        } else if (j < 84) {                // st2 (64,64,64,64) F=8
            int jj = j - 56;
            int si = jj >> 1;
            int tt = (jj & 1) ? -1 : 1;
            int tb = pidx[p][12], tv = pidx[p][13];
            int a  = (tb + c_S14[si][0] + 64) & 63;
            int bb = (tb + c_S14[si][1] + 64) & 63;
            int c  = (tb + c_S14[si][2] + 64) & 63;
            int dd = (tv + tt + 64) & 63;
            b = ((((((a << 6) | bb) << 6) | c) << 6) | dd) << 3;
        } else {                            // tf3 (4,4,4,65536) F=8
            int jj = j - 84;
            int ci = jj / 11;
            int ti = jj - ci * 11;
            int tb = pidx[p][12], tv = pidx[p][13];
            int a  = (tb + c_CORNER[ci][0] + 4) & 3;
            int bb = (tb + c_CORNER[ci][1] + 4) & 3;
            int c  = (tb + c_CORNER[ci][2] + 4) & 3;
            int dd = (tv + c_ETEMP[ti] + 65536) & 65535;
            b = ((((((a << 2) | bb) << 2) | c) << 16) | dd) << 3;
        }
        bases[e] = b;
    }
    __syncthreads();

    float acc[4][4];
#pragma unroll
    for (int i = 0; i < 4; i++)
#pragma unroll
        for (int j = 0; j < 4; j++) acc[i][j] = 0.f;
    float ss_lo = 0.f, ss_hi = 0.f;

    const int lm_row = ((lane >> 3) & 1) * 8 + (lane & 7);
    const int lm_kof = (lane >> 4) * 4;

    // ---- prologue: gather chunk 0 into regs (2 float4 per thread) ---------
    float4 v[2];
#pragma unroll
    for (int j = 0; j < 2; j++) {
        int i  = tid + j * TPB;
        int p  = i >> 5;
        int k4 = (i & 31) << 2;
        v[j] = gather4b(k4, bases + p * NB, T0, T1, T2, T3, S1t, S2t, TF);
    }

    for (int ch = 0; ch < NCH; ch++) {
        uint32_t* buf = As + (ch & 1) * (MPTS * SA);
        const int kb  = ch * KC;

        // ---- STS: raw fp32 bits -------------------------------------------
#pragma unroll
        for (int j = 0; j < 2; j++) {
            int i  = tid + j * TPB;
            int p  = i >> 5;
            int k4 = (i & 31) << 2;
            *reinterpret_cast<float4*>(&buf[p * SA + k4]) = v[j];
        }
        __syncthreads();

        // ---- prefetch next chunk (overlaps mma) ---------------------------
        if (ch + 1 < NCH) {
#pragma unroll
            for (int j = 0; j < 2; j++) {
                int i  = tid + j * TPB;
                int p  = i >> 5;
                int k4 = (i & 31) << 2;
                v[j] = gather4b(kb + KC + k4, bases + p * NB, T0, T1, T2, T3, S1t, S2t, TF);
            }
        }

        // ---- mma: warp covers k8 in [kq*4, +4), n [nh*32, +32) ------------
#pragma unroll
        for (int g = 0; g < 4; g++) {
            int K8l = kq * 4 + g;           // k8 group within chunk [0,16)
            int kk  = K8l * 8;
            uint32_t r0, r1, r2, r3;
            uint32_t addr = s2u(&buf[lm_row * SA + kk + lm_kof]);
            asm volatile("ldmatrix.sync.aligned.m8n8.x4.shared.b16 {%0,%1,%2,%3}, [%4];"
                         : "=r"(r0), "=r"(r1), "=r"(r2), "=r"(r3) : "r"(addr));
            float f0 = fmaxf(__uint_as_float(r0), 0.f);
            float f1 = fmaxf(__uint_as_float(r1), 0.f);
            float f2 = fmaxf(__uint_as_float(r2), 0.f);
            float f3 = fmaxf(__uint_as_float(r3), 0.f);
            if (nh == 0) {                  // avoid double-count across n-halves
                ss_lo += f0 * f0 + f2 * f2;
                ss_hi += f1 * f1 + f3 * f3;
            }
            uint32_t a0 = f2tf32(f0), a1 = f2tf32(f1);
            uint32_t a2 = f2tf32(f2), a3 = f2tf32(f3);
            const uint4* Wk = g_Wf4 + ((size_t)(ch * 16 + K8l) << 7) + lane;
#pragma unroll
            for (int q = 0; q < 2; q++) {
                uint4 bq = Wk[(2 * nh + q) * 32];
                mma8(acc[2 * q],     a0, a1, a2, a3, bq.x, bq.y);
                mma8(acc[2 * q + 1], a0, a1, a2, a3, bq.z, bq.w);
            }
        }
    }

    // ---- sumsq reduction (nh==0 warps only contributed) -------------------
    ss_lo += __shfl_xor_sync(0xffffffffu, ss_lo, 1);
    ss_lo += __shfl_xor_sync(0xffffffffu, ss_lo, 2);
    ss_hi += __shfl_xor_sync(0xffffffffu, ss_hi, 1);
    ss_hi += __shfl_xor_sync(0xffffffffu, ss_hi, 2);
    if (nh == 0 && (lane & 3) == 0) {
        atomicAdd(&sumsq_s[lane >> 2], ss_lo);
        atomicAdd(&sumsq_s[8 + (lane >> 2)], ss_hi);
    }

    // ---- cross-k acc reduction (serialized by kq; both nh in parallel) ----
    {
        int row = lane >> 2;
        int cb  = nh * 32 + (lane & 3) * 2;
        if (kq == 3) {
#pragma unroll
            for (int nt = 0; nt < 4; nt++) {
                int col = cb + nt * 8;
                Rbuf[row * RS + col]           = acc[nt][0];
                Rbuf[row * RS + col + 1]       = acc[nt][1];
                Rbuf[(row + 8) * RS + col]     = acc[nt][2];
                Rbuf[(row + 8) * RS + col + 1] = acc[nt][3];
            }
        }
        __syncthreads();
        if (kq == 2) {
#pragma unroll
            for (int nt = 0; nt < 4; nt++) {
                int col = cb + nt * 8;
                Rbuf[row * RS + col]           += acc[nt][0];
                Rbuf[row * RS + col + 1]       += acc[nt][1];
                Rbuf[(row + 8) * RS + col]     += acc[nt][2];
                Rbuf[(row + 8) * RS + col + 1] += acc[nt][3];
            }
        }
        __syncthreads();
        if (kq == 1) {
#pragma unroll
            for (int nt = 0; nt < 4; nt++) {
                int col = cb + nt * 8;
                Rbuf[row * RS + col]           += acc[nt][0];
                Rbuf[row * RS + col + 1]       += acc[nt][1];
                Rbuf[(row + 8) * RS + col]     += acc[nt][2];
                Rbuf[(row + 8) * RS + col + 1] += acc[nt][3];
            }
        }
        __syncthreads();
        if (kq == 0) {
            float inv0 = 1.0f / (sqrtf(sumsq_s[row] * (1.0f / 12240.0f)) + 1e-8f);
            float inv1 = 1.0f / (sqrtf(sumsq_s[row + 8] * (1.0f / 12240.0f)) + 1e-8f);
#pragma unroll
            for (int nt = 0; nt < 4; nt++) {
                int col = cb + nt * 8;
                Rbuf[row * RS + col]           = fmaxf((acc[nt][0] + Rbuf[row * RS + col]) * inv0, 0.f);
                Rbuf[row * RS + col + 1]       = fmaxf((acc[nt][1] + Rbuf[row * RS + col + 1]) * inv0, 0.f);
                Rbuf[(row + 8) * RS + col]     = fmaxf((acc[nt][2] + Rbuf[(row + 8) * RS + col]) * inv1, 0.f);
                Rbuf[(row + 8) * RS + col + 1] = fmaxf((acc[nt][3] + Rbuf[(row + 8) * RS + col + 1]) * inv1, 0.f);
            }
        }
    }
    __syncthreads();

    // ---- final tiny layer + sigmoid ---------------------------------------
    if (tid < MPTS) {
        int gp = p0 + tid;
        float o0 = b_final[0], o1 = b_final[1], o2 = b_final[2], o3 = b_final[3];
#pragma unroll 8
        for (int i = 0; i < 64; i++) {
            float h = Rbuf[tid * RS + i];
            float4 wf = *reinterpret_cast<const float4*>(w_final + i * 4);
            o0 += h * wf.x; o1 += h * wf.y; o2 += h * wf.z; o3 += h * wf.w;
        }
#pragma unroll
        for (int c = 0; c < 3; c++) {
            float dv = d_dir[gp * 3 + c];
            float4 wf = *reinterpret_cast<const float4*>(w_final + (64 + c) * 4);
            o0 += dv * wf.x; o1 += dv * wf.y; o2 += dv * wf.z; o3 += dv * wf.w;
        }
        {
            float tv = d_t[gp];
            float4 wf = *reinterpret_cast<const float4*>(w_final + 67 * 4);
            o0 += tv * wf.x; o1 += tv * wf.y; o2 += tv * wf.z; o3 += tv * wf.w;
        }
        d_out[gp * 4 + 0] = 1.0f / (1.0f + expf(-o0));
        d_out[gp * 4 + 1] = 1.0f / (1.0f + expf(-o1));
        d_out[gp * 4 + 2] = 1.0f / (1.0f + expf(-o2));
        d_out[gp * 4 + 3] = 1.0f / (1.0f + expf(-o3));
    }
}

extern "C" void kernel_launch(void* const* d_in, const int* in_sizes, int n_in,
                              void* d_out, int out_size) {
    const float* pos       = (const float*)d_in[0];
    const float* dirv      = (const float*)d_in[1];
    const float* t         = (const float*)d_in[2];
    const float* table0    = (const float*)d_in[3];
    const float* table1    = (const float*)d_in[4];
    const float* table2    = (const float*)d_in[5];
    const float* table3    = (const float*)d_in[6];
    const float* st1       = (const float*)d_in[7];
    const float* st2       = (const float*)d_in[8];
    const float* tf3       = (const float*)d_in[9];
    const float* rms_scale = (const float*)d_in[10];
    const float* w_down    = (const float*)d_in[11];
    const float* w_final   = (const float*)d_in[12];
    const float* b_final   = (const float*)d_in[13];
    float* out = (float*)d_out;

    wf_precompute_kernel<<<(NK8 * 4 * 32 + 255) / 256, 256>>>(w_down, rms_scale);
    stlt_fused_kernel<<<8192 / MPTS, TPB>>>(
        pos, dirv, t, table0, table1, table2, table3, st1, st2, tf3,
        w_final, b_final, out);
}